// round 4
// baseline (speedup 1.0000x reference)
#include <cuda_runtime.h>
#include <cstdint>

#define HH 128
#define WW 192
#define CC_TOT 256
#define BB 8
#define TILE_W 32
#define TILE_H 16
#define HALO_W 40
#define HALO_H 24
#define CHUNK 4
#define NCHUNK (CC_TOT / CHUNK)
#define NT 128
#define PLANE ((size_t)HH * WW)

#define PSEC 3856
#define PAD_REL 3840
#define PREV_BUF (CHUNK * PSEC)
#define CURR_BUF (CHUNK * TILE_H * TILE_W * 4)
#define SM_PREV 0
#define SM_CURR (3 * PREV_BUF)
#define SM_SSP  (SM_CURR + 3 * CURR_BUF)
#define SMEM_BYTES (SM_SSP + HALO_H * HALO_W * 4)

typedef unsigned long long u64;

__device__ __forceinline__ void F2(u64 &d, u64 a, u64 b) {
    asm("fma.rn.f32x2 %0, %1, %2, %0;" : "+l"(d) : "l"(a), "l"(b));
}
__device__ __forceinline__ u64 M2(u64 a, u64 b) {
    u64 d; asm("mul.rn.f32x2 %0, %1, %2;" : "=l"(d) : "l"(a), "l"(b)); return d;
}
__device__ __forceinline__ u64 PK(unsigned a, unsigned b) {
    u64 d; asm("mov.b64 %0, {%1, %2};" : "=l"(d) : "r"(a), "r"(b)); return d;
}
__device__ __forceinline__ unsigned LOW(u64 a) {
    unsigned l, h; asm("mov.b64 {%0, %1}, %2;" : "=r"(l), "=r"(h) : "l"(a)); return l;
}
__device__ __forceinline__ unsigned HIW(u64 a) {
    unsigned l, h; asm("mov.b64 {%0, %1}, %2;" : "=r"(l), "=r"(h) : "l"(a)); return h;
}
__device__ __forceinline__ float FL(u64 a) { return __uint_as_float(LOW(a)); }
__device__ __forceinline__ float FH(u64 a) { return __uint_as_float(HIW(a)); }
__device__ __forceinline__ void cp16(uint32_t dst, const void* src, int szbytes) {
    asm volatile("cp.async.cg.shared.global [%0], [%1], 16, %2;\n"
                 :: "r"(dst), "l"(src), "r"(szbytes) : "memory");
}
__device__ __forceinline__ ulonglong2 LD2(const void* p) {
    return *reinterpret_cast<const ulonglong2*>(p);
}
__device__ __forceinline__ float LDF(const void* p) {
    return *reinterpret_cast<const float*>(p);
}

__global__ void __launch_bounds__(NT, 3)
corr_kernel(const float* __restrict__ curr, const float* __restrict__ prev,
            float* __restrict__ out)
{
    extern __shared__ char smem[];

    const int tid = threadIdx.x;
    const int g   = tid & 7;
    const int tx4 = g * 4;
    const int ty  = tid >> 3;
    const int x0  = blockIdx.x * TILE_W;
    const int y0  = blockIdx.y * TILE_H;
    const int bb  = blockIdx.z;

    const char* currB = (const char*)(curr + (size_t)bb * CC_TOT * PLANE);
    const char* prevB = (const char*)(prev + (size_t)bb * CC_TOT * PLANE);

    const uint32_t smA = (uint32_t)__cvta_generic_to_shared(smem);

    // ---- staging precompute ----
    const int sy0 = tid / 10,         sx0 = tid - sy0 * 10;
    const int sy1 = (tid + 128) / 10, sx1 = (tid + 128) - sy1 * 10;
    const int gy0 = y0 - 4 + sy0, gx0 = x0 - 4 + sx0 * 4;
    const int gy1 = y0 - 4 + sy1, gx1 = x0 - 4 + sx1 * 4;
    const bool ok0 = ((unsigned)gy0 < HH) && ((unsigned)gx0 < WW);
    const bool ok1 = ((unsigned)gy1 < HH) && ((unsigned)gx1 < WW) && (tid < 112);
    const int pixOff0 = ok0 ? (gy0 * WW + gx0) * 4 : 0;
    const int pixOff1 = ok1 ? (gy1 * WW + gx1) * 4 : 0;
    const int sz0 = ok0 ? 16 : 0;
    const int sz1 = ok1 ? 16 : 0;
    const uint32_t rel0 = (uint32_t)tid * 16;
    const uint32_t rel1 = (tid < 112) ? (uint32_t)(tid + 128) * 16 : (uint32_t)PAD_REL;
    const int cpixOff = ((y0 + ty) * WW + x0 + tx4) * 4;

    // ---- sq fallback slot ----
    int s;
    if (tid < 40)       s = tid;
    else if (tid < 80)  s = 200 + (tid - 40);
    else if (tid < 112) { int i = tid - 80; s = (4 + (i >> 1)) * 10 + (i & 1) * 9; }
    else                s = 0;
    const uint32_t sOff = (uint32_t)s * 16;

    // ---- accumulators ----
    // packed (27 offsets): [0..4]=dy-4, [5..9]=dy-2, [10]=dy-1/dx0,
    // [11..15]=dy0 dx even, [16]=dy1/dx0, [17..21]=dy2, [22..26]=dy4
    u64 pL[27], pH[27];
    #pragma unroll
    for (int o = 0; o < 27; o++) { pL[o] = 0ull; pH[o] = 0ull; }
    // scalar (6 offsets x 4 px): S0=o10, S1=o12, S2=o15, S3=o17, S4=o20, S5=o22
    float aS[24];
    #pragma unroll
    for (int i = 0; i < 24; i++) aS[i] = 0.f;
    u64 ssqL = 0ull, ssqH = 0ull;
    u64 sqML = 0ull, sqMH = 0ull;
    u64 sqFL = 0ull, sqFH = 0ull;

    auto issue = [&](const char* srcP, const char* srcC, uint32_t dP, uint32_t dC) {
        #pragma unroll
        for (int cc = 0; cc < CHUNK; cc++) {
            const size_t so = (size_t)cc * PLANE * 4;
            cp16(dP + cc * PSEC + rel0, srcP + so + pixOff0, sz0);
            cp16(dP + cc * PSEC + rel1, srcP + so + pixOff1, sz1);
            cp16(dC + cc * 2048 + rel0, srcC + so + cpixOff, 16);
        }
        asm volatile("cp.async.commit_group;\n" ::: "memory");
    };

    issue(prevB, currB, smA + SM_PREV, smA + SM_CURR);
    issue(prevB + (size_t)CHUNK * PLANE * 4, currB + (size_t)CHUNK * PLANE * 4,
          smA + SM_PREV + PREV_BUF, smA + SM_CURR + CURR_BUF);

    const char* srcPs = prevB + (size_t)2 * CHUNK * PLANE * 4;
    const char* srcCs = currB + (size_t)2 * CHUNK * PLANE * 4;
    int bC = 0, bS = 2;

    const int rowOff = (ty * HALO_W + tx4) * 4;
    const int cvOff  = (ty * TILE_W + tx4) * 4;

#define PROW(O, Q0, Q1, Q2) do { \
    F2(pL[O + 0], cvL, (Q0).x); F2(pH[O + 0], cvH, (Q0).y); \
    F2(pL[O + 1], cvL, (Q0).y); F2(pH[O + 1], cvH, (Q1).x); \
    F2(pL[O + 2], cvL, (Q1).x); F2(pH[O + 2], cvH, (Q1).y); \
    F2(pL[O + 3], cvL, (Q1).y); F2(pH[O + 3], cvH, (Q2).x); \
    F2(pL[O + 4], cvL, (Q2).x); F2(pH[O + 4], cvH, (Q2).y); } while (0)

// dx=-1 (base SB) and dx=+1 (SB+4) scalar FMAs given f3..f8
#define SMID(SB, f3v, f4v, f5v, f6v, f7v, f8v) do { \
    aS[SB + 0] = fmaf(cv0, (f3v), aS[SB + 0]); \
    aS[SB + 1] = fmaf(cv1, (f4v), aS[SB + 1]); \
    aS[SB + 2] = fmaf(cv2, (f5v), aS[SB + 2]); \
    aS[SB + 3] = fmaf(cv3, (f6v), aS[SB + 3]); \
    aS[SB + 4] = fmaf(cv0, (f5v), aS[SB + 4]); \
    aS[SB + 5] = fmaf(cv1, (f6v), aS[SB + 5]); \
    aS[SB + 6] = fmaf(cv2, (f7v), aS[SB + 6]); \
    aS[SB + 7] = fmaf(cv3, (f8v), aS[SB + 7]); } while (0)

    #pragma unroll 1
    for (int k = 0; k < NCHUNK; k++) {
        if (k < NCHUNK - 1) asm volatile("cp.async.wait_group 1;\n" ::: "memory");
        else                asm volatile("cp.async.wait_group 0;\n" ::: "memory");
        __syncthreads();

        if (k < NCHUNK - 2) {
            issue(srcPs, srcCs, smA + SM_PREV + bS * PREV_BUF, smA + SM_CURR + bS * CURR_BUF);
            srcPs += (size_t)CHUNK * PLANE * 4;
            srcCs += (size_t)CHUNK * PLANE * 4;
            bS = (bS == 2) ? 0 : bS + 1;
        }

        const char* pbuf = smem + SM_PREV + bC * PREV_BUF;
        const char* cbuf = smem + SM_CURR + bC * CURR_BUF;

        #pragma unroll
        for (int cc = 0; cc < CHUNK; cc++) {
            const char* secB = pbuf + cc * PSEC;
            const char* rowB = secB + rowOff;

            // early independent loads: CV, fallback, rows -4 and -2
            const ulonglong2 CV = LD2(cbuf + cc * 2048 + cvOff);
            const ulonglong2 FB = LD2(secB + sOff);
            ulonglong2 a0 = LD2(rowB +   0), a1 = LD2(rowB +  16), a2 = LD2(rowB +  32);
            ulonglong2 b0 = LD2(rowB + 320), b1 = LD2(rowB + 336), b2 = LD2(rowB + 352);

            const u64 cvL = CV.x, cvH = CV.y;
            const float cv0 = FL(cvL), cv1 = FH(cvL), cv2 = FL(cvH), cv3 = FH(cvH);
            F2(ssqL, cvL, cvL); F2(ssqH, cvH, cvH);
            F2(sqFL, FB.x, FB.x); F2(sqFH, FB.y, FB.y);

            PROW(0, a0, a1, a2);                               // dy=-4

            ulonglong2 m1 = LD2(rowB + 496);                   // dy=-1 loads
            float ms3 = LDF(rowB + 492), ms8 = LDF(rowB + 512);

            PROW(5, b0, b1, b2);                               // dy=-2

            a0 = LD2(rowB + 640); a1 = LD2(rowB + 656); a2 = LD2(rowB + 672);   // dy=0 loads

            F2(pL[10], cvL, m1.x); F2(pH[10], cvH, m1.y);      // dy=-1
            SMID(0, ms3, FL(m1.x), FH(m1.x), FL(m1.y), FH(m1.y), ms8);

            ulonglong2 n1 = LD2(rowB + 816);                   // dy=+1 loads
            float ns3 = LDF(rowB + 812), ns8 = LDF(rowB + 832);

            F2(sqML, a1.x, a1.x); F2(sqMH, a1.y, a1.y);        // dy=0
            PROW(11, a0, a1, a2);
            SMID(8, FH(a0.y), FL(a1.x), FH(a1.x), FL(a1.y), FH(a1.y), FL(a2.x));

            b0 = LD2(rowB + 960); b1 = LD2(rowB + 976); b2 = LD2(rowB + 992);   // dy=2 loads

            F2(pL[16], cvL, n1.x); F2(pH[16], cvH, n1.y);      // dy=+1
            SMID(16, ns3, FL(n1.x), FH(n1.x), FL(n1.y), FH(n1.y), ns8);

            a0 = LD2(rowB + 1280); a1 = LD2(rowB + 1296); a2 = LD2(rowB + 1312); // dy=4 loads

            PROW(17, b0, b1, b2);                              // dy=+2
            PROW(22, a0, a1, a2);                              // dy=+4
        }
        bC = (bC == 2) ? 0 : bC + 1;
    }

    // ---- epilogue: inverse norms into sspInv ----
    {
        float* ssp = (float*)(smem + SM_SSP);
        {
            const float a = FL(sqML), b = FH(sqML), c = FL(sqMH), d = FH(sqMH);
            float4 r;
            r.x = a > 0.f ? rsqrtf(a) : 0.f;
            r.y = b > 0.f ? rsqrtf(b) : 0.f;
            r.z = c > 0.f ? rsqrtf(c) : 0.f;
            r.w = d > 0.f ? rsqrtf(d) : 0.f;
            ((float4*)ssp)[(ty + 4) * 10 + g + 1] = r;
        }
        if (tid < 112) {
            const float a = FL(sqFL), b = FH(sqFL), c = FL(sqFH), d = FH(sqFH);
            float4 r;
            r.x = a > 0.f ? rsqrtf(a) : 0.f;
            r.y = b > 0.f ? rsqrtf(b) : 0.f;
            r.z = c > 0.f ? rsqrtf(c) : 0.f;
            r.w = d > 0.f ? rsqrtf(d) : 0.f;
            ((float4*)ssp)[s] = r;
        }
    }
    __syncthreads();

    const float ic0 = rsqrtf(FL(ssqL));
    const float ic1 = rsqrtf(FH(ssqL));
    const float ic2 = rsqrtf(FL(ssqH));
    const float ic3 = rsqrtf(FH(ssqH));
    const u64 invL = PK(__float_as_uint(ic0), __float_as_uint(ic1));
    const u64 invH = PK(__float_as_uint(ic2), __float_as_uint(ic3));

    const char* srow = smem + SM_SSP + rowOff;
    char* outPix = (char*)(out + ((size_t)bb * 33 * HH + (y0 + ty)) * WW + x0 + tx4);

#define ESTP(OPL, PI, BL, BH) do { \
    ulonglong2 _r; \
    _r.x = M2(M2(pL[PI], invL), (BL)); \
    _r.y = M2(M2(pH[PI], invH), (BH)); \
    *(ulonglong2*)(outPix + (size_t)(OPL) * (PLANE * 4)) = _r; } while (0)

#define ESTS(OPL, SB, J0, J1, J2, J3v) do { \
    float4 _r; \
    _r.x = aS[SB + 0] * ic0 * (J0); \
    _r.y = aS[SB + 1] * ic1 * (J1); \
    _r.z = aS[SB + 2] * ic2 * (J2); \
    _r.w = aS[SB + 3] * ic3 * (J3v); \
    *(float4*)(outPix + (size_t)(OPL) * (PLANE * 4)) = _r; } while (0)

#define EROWF(R, OPL, PI) do { \
    const ulonglong2 q0 = LD2(srow + (R) * 160), q1 = LD2(srow + (R) * 160 + 16), \
                     q2 = LD2(srow + (R) * 160 + 32); \
    ESTP(OPL + 0, PI + 0, q0.x, q0.y); \
    ESTP(OPL + 1, PI + 1, q0.y, q1.x); \
    ESTP(OPL + 2, PI + 2, q1.x, q1.y); \
    ESTP(OPL + 3, PI + 3, q1.y, q2.x); \
    ESTP(OPL + 4, PI + 4, q2.x, q2.y); } while (0)

    EROWF(0, 0, 0);     // dy=-4: o0..o4
    EROWF(2, 5, 5);     // dy=-2: o5..o9
    {                   // dy=-1: o10,o11,o12
        const ulonglong2 q1 = LD2(srow + 496);
        const float j3 = LDF(srow + 492), j8 = LDF(srow + 512);
        ESTS(10, 0, j3, FL(q1.x), FH(q1.x), FL(q1.y));
        ESTP(11, 10, q1.x, q1.y);
        ESTS(12, 4, FH(q1.x), FL(q1.y), FH(q1.y), j8);
    }
    {                   // dy=0: o13..o19
        const ulonglong2 q0 = LD2(srow + 640), q1 = LD2(srow + 656), q2 = LD2(srow + 672);
        ESTP(13, 11, q0.x, q0.y);
        ESTP(14, 12, q0.y, q1.x);
        ESTS(15, 8, FH(q0.y), FL(q1.x), FH(q1.x), FL(q1.y));
        ESTP(16, 13, q1.x, q1.y);
        ESTS(17, 12, FH(q1.x), FL(q1.y), FH(q1.y), FL(q2.x));
        ESTP(18, 14, q1.y, q2.x);
        ESTP(19, 15, q2.x, q2.y);
    }
    {                   // dy=+1: o20,o21,o22
        const ulonglong2 q1 = LD2(srow + 816);
        const float j3 = LDF(srow + 812), j8 = LDF(srow + 832);
        ESTS(20, 16, j3, FL(q1.x), FH(q1.x), FL(q1.y));
        ESTP(21, 16, q1.x, q1.y);
        ESTS(22, 20, FH(q1.x), FL(q1.y), FH(q1.y), j8);
    }
    EROWF(6, 23, 17);   // dy=+2: o23..o27
    EROWF(8, 28, 22);   // dy=+4: o28..o32
}

extern "C" void kernel_launch(void* const* d_in, const int* in_sizes, int n_in,
                              void* d_out, int out_size)
{
    const float* curr = (const float*)d_in[0];
    const float* prev = (const float*)d_in[1];
    float* out = (float*)d_out;

    cudaFuncSetAttribute(corr_kernel, cudaFuncAttributeMaxDynamicSharedMemorySize, SMEM_BYTES);

    dim3 grid(WW / TILE_W, HH / TILE_H, BB);
    corr_kernel<<<grid, NT, SMEM_BYTES>>>(curr, prev, out);
}

// round 5
// speedup vs baseline: 1.2337x; 1.2337x over previous
#include <cuda_runtime.h>
#include <cstdint>

#define HH 128
#define WW 192
#define CC_TOT 256
#define BB 8
#define TILE_W 32
#define TILE_H 16
#define HALO_W 40
#define HALO_H 24
#define CHUNK 4
#define NCHUNK (CC_TOT / CHUNK)
#define NT 256
#define PLANE ((size_t)HH * WW)

#define PSEC (HALO_H * HALO_W * 4)                    // 3840
#define PREV_BUF (CHUNK * PSEC)                       // 15360
#define CURR_BUF (CHUNK * TILE_H * TILE_W * 4)        // 8192
#define SM_PREV 0
#define SM_CURR (3 * PREV_BUF)                        // 46080
#define SM_SSP  (SM_CURR + 3 * CURR_BUF)              // 70656
#define SMEM_BYTES (SM_SSP + HALO_H * HALO_W * 4)     // 74496 -> 2 CTAs/SM (smem), RF-capped too

typedef unsigned long long u64;

__device__ __forceinline__ void F2(u64 &d, u64 a, u64 b) {
    asm("fma.rn.f32x2 %0, %1, %2, %0;" : "+l"(d) : "l"(a), "l"(b));
}
__device__ __forceinline__ u64 M2(u64 a, u64 b) {
    u64 d; asm("mul.rn.f32x2 %0, %1, %2;" : "=l"(d) : "l"(a), "l"(b)); return d;
}
__device__ __forceinline__ u64 PK(unsigned a, unsigned b) {
    u64 d; asm("mov.b64 %0, {%1, %2};" : "=l"(d) : "r"(a), "r"(b)); return d;
}
__device__ __forceinline__ unsigned LOW(u64 a) {
    unsigned l, h; asm("mov.b64 {%0, %1}, %2;" : "=r"(l), "=r"(h) : "l"(a)); return l;
}
__device__ __forceinline__ unsigned HIW(u64 a) {
    unsigned l, h; asm("mov.b64 {%0, %1}, %2;" : "=r"(l), "=r"(h) : "l"(a)); return h;
}
__device__ __forceinline__ float FL(u64 a) { return __uint_as_float(LOW(a)); }
__device__ __forceinline__ float FH(u64 a) { return __uint_as_float(HIW(a)); }
__device__ __forceinline__ void cp16(uint32_t dst, const void* src, int szbytes) {
    asm volatile("cp.async.cg.shared.global [%0], [%1], 16, %2;\n"
                 :: "r"(dst), "l"(src), "r"(szbytes) : "memory");
}
__device__ __forceinline__ ulonglong2 LD2(const void* p) {
    return *reinterpret_cast<const ulonglong2*>(p);
}
__device__ __forceinline__ u64 LD1(const void* p) {
    return *reinterpret_cast<const u64*>(p);
}

__global__ void __launch_bounds__(NT, 2)
corr_kernel(const float* __restrict__ curr, const float* __restrict__ prev,
            float* __restrict__ out)
{
    extern __shared__ char smem[];

    const int tid = threadIdx.x;
    const int wg  = tid >> 7;          // warpgroup: 0 or 1
    const int wt  = tid & 127;         // thread within wg
    const int g   = wt & 7;
    const int tx4 = g * 4;
    const int ty  = wt >> 3;
    const int x0  = blockIdx.x * TILE_W;
    const int y0  = blockIdx.y * TILE_H;
    const int bb  = blockIdx.z;

    const char* currB = (const char*)(curr + (size_t)bb * CC_TOT * PLANE);
    const char* prevB = (const char*)(prev + (size_t)bb * CC_TOT * PLANE);
    const uint32_t smA = (uint32_t)__cvta_generic_to_shared(smem);

    // ---- staging precompute ----
    // prev: 240 f4 slots per cc, thread tid<240 owns slot tid
    const int psy = tid / 10, psx = tid - psy * 10;
    const int pgy = y0 - 4 + psy, pgx = x0 - 4 + psx * 4;
    const bool pok = (tid < 240) && ((unsigned)pgy < HH) && ((unsigned)pgx < WW);
    const int pOff = pok ? (pgy * WW + pgx) * 4 : 0;
    const int psz  = pok ? 16 : 0;
    const bool doP = (tid < 240);
    // curr: 128 f4 slots, staged by threads 128..255 (slot = tid-128)
    const bool doC = (tid >= 128);
    const int cslot = tid - 128;
    const int cOff = doC ? (((y0 + (cslot >> 3)) * WW) + x0 + (cslot & 7) * 4) * 4 : 0;

    // sq slot (prev L2-norms): thread<240 owns f4 slot tid; others dummy-read slot 0
    const uint32_t sOff = (uint32_t)((tid < 240) ? tid : 0) * 16;

    // ---- accumulators ----
    // wg0: 16 offsets -> pairs p[0..15]; wg1: 17 -> p[0..16]
    u64 pL[17], pH[17];
    #pragma unroll
    for (int o = 0; o < 17; o++) { pL[o] = 0ull; pH[o] = 0ull; }
    u64 ssqL = 0ull, ssqH = 0ull;
    u64 sqL = 0ull, sqH = 0ull;

    auto issue = [&](const char* srcP, const char* srcC, uint32_t dP, uint32_t dC) {
        #pragma unroll
        for (int cc = 0; cc < CHUNK; cc++) {
            const size_t so = (size_t)cc * PLANE * 4;
            if (doP) cp16(dP + cc * PSEC + tid * 16, srcP + so + pOff, psz);
            if (doC) cp16(dC + cc * 2048 + cslot * 16, srcC + so + cOff, 16);
        }
        asm volatile("cp.async.commit_group;\n" ::: "memory");
    };

    issue(prevB, currB, smA + SM_PREV, smA + SM_CURR);
    issue(prevB + (size_t)CHUNK * PLANE * 4, currB + (size_t)CHUNK * PLANE * 4,
          smA + SM_PREV + PREV_BUF, smA + SM_CURR + CURR_BUF);

    const char* srcPs = prevB + (size_t)2 * CHUNK * PLANE * 4;
    const char* srcCs = currB + (size_t)2 * CHUNK * PLANE * 4;
    int bC = 0, bS = 2;

    const int rowOff = (ty * HALO_W + tx4) * 4;
    const int cvOff  = (ty * TILE_W + tx4) * 4;

#define PROW(O, Q0, Q1, Q2) do { \
    F2(pL[O + 0], cvL, (Q0).x); F2(pH[O + 0], cvH, (Q0).y); \
    F2(pL[O + 1], cvL, (Q0).y); F2(pH[O + 1], cvH, (Q1).x); \
    F2(pL[O + 2], cvL, (Q1).x); F2(pH[O + 2], cvH, (Q1).y); \
    F2(pL[O + 3], cvL, (Q1).y); F2(pH[O + 3], cvH, (Q2).x); \
    F2(pL[O + 4], cvL, (Q2).x); F2(pH[O + 4], cvH, (Q2).y); } while (0)

// dy row with only dx=-1,0,1 (loads a1=s2s3, q1=s4..7, a4=s8s9)
#define PMID(O, A1, Q1, A4) do { \
    const u64 P34 = PK(HIW(A1), LOW((Q1).x)); \
    const u64 P56 = PK(HIW((Q1).x), LOW((Q1).y)); \
    const u64 P78 = PK(HIW((Q1).y), LOW(A4)); \
    F2(pL[O + 0], cvL, P34);    F2(pH[O + 0], cvH, P56); \
    F2(pL[O + 1], cvL, (Q1).x); F2(pH[O + 1], cvH, (Q1).y); \
    F2(pL[O + 2], cvL, P56);    F2(pH[O + 2], cvH, P78); } while (0)

    #pragma unroll 1
    for (int k = 0; k < NCHUNK; k++) {
        if (k < NCHUNK - 1) asm volatile("cp.async.wait_group 1;\n" ::: "memory");
        else                asm volatile("cp.async.wait_group 0;\n" ::: "memory");
        __syncthreads();

        if (k < NCHUNK - 2) {
            issue(srcPs, srcCs, smA + SM_PREV + bS * PREV_BUF, smA + SM_CURR + bS * CURR_BUF);
            srcPs += (size_t)CHUNK * PLANE * 4;
            srcCs += (size_t)CHUNK * PLANE * 4;
            bS = (bS == 2) ? 0 : bS + 1;
        }

        const char* pbuf = smem + SM_PREV + bC * PREV_BUF;
        const char* cbuf = smem + SM_CURR + bC * CURR_BUF;

        if (wg == 0) {
            #pragma unroll
            for (int cc = 0; cc < CHUNK; cc++) {
                const char* secB = pbuf + cc * PSEC;
                const char* rowB = secB + rowOff;
                const ulonglong2 CV = LD2(cbuf + cc * 2048 + cvOff);
                const ulonglong2 SQ = LD2(secB + sOff);
                const u64 cvL = CV.x, cvH = CV.y;
                F2(ssqL, cvL, cvL); F2(ssqH, cvH, cvH);
                F2(sqL, SQ.x, SQ.x); F2(sqH, SQ.y, SQ.y);

                {   // dy=-4 : p0..4
                    const ulonglong2 q0 = LD2(rowB), q1 = LD2(rowB + 16), q2 = LD2(rowB + 32);
                    PROW(0, q0, q1, q2);
                }
                {   // dy=-2 : p5..9
                    const ulonglong2 q0 = LD2(rowB + 320), q1 = LD2(rowB + 336), q2 = LD2(rowB + 352);
                    PROW(5, q0, q1, q2);
                }
                {   // dy=-1 : p10..12
                    const u64 a1 = LD1(rowB + 488);
                    const ulonglong2 q1 = LD2(rowB + 496);
                    const u64 a4 = LD1(rowB + 512);
                    PMID(10, a1, q1, a4);
                }
                {   // dy=0, dx=-4,-2,-1 : p13..15
                    const ulonglong2 q0 = LD2(rowB + 640), q1 = LD2(rowB + 656);
                    F2(pL[13], cvL, q0.x); F2(pH[13], cvH, q0.y);
                    F2(pL[14], cvL, q0.y); F2(pH[14], cvH, q1.x);
                    const u64 P34 = PK(HIW(q0.y), LOW(q1.x));
                    const u64 P56 = PK(HIW(q1.x), LOW(q1.y));
                    F2(pL[15], cvL, P34); F2(pH[15], cvH, P56);
                }
            }
        } else {
            #pragma unroll
            for (int cc = 0; cc < CHUNK; cc++) {
                const char* secB = pbuf + cc * PSEC;
                const char* rowB = secB + rowOff;
                const ulonglong2 CV = LD2(cbuf + cc * 2048 + cvOff);
                const ulonglong2 SQ = LD2(secB + sOff);
                const u64 cvL = CV.x, cvH = CV.y;
                F2(ssqL, cvL, cvL); F2(ssqH, cvH, cvH);
                F2(sqL, SQ.x, SQ.x); F2(sqH, SQ.y, SQ.y);

                {   // dy=0, dx=0,1,2,4 : p0..3
                    const ulonglong2 q1 = LD2(rowB + 656), q2 = LD2(rowB + 672);
                    F2(pL[0], cvL, q1.x); F2(pH[0], cvH, q1.y);
                    const u64 P56 = PK(HIW(q1.x), LOW(q1.y));
                    const u64 P78 = PK(HIW(q1.y), LOW(q2.x));
                    F2(pL[1], cvL, P56); F2(pH[1], cvH, P78);
                    F2(pL[2], cvL, q1.y); F2(pH[2], cvH, q2.x);
                    F2(pL[3], cvL, q2.x); F2(pH[3], cvH, q2.y);
                }
                {   // dy=+1 : p4..6
                    const u64 a1 = LD1(rowB + 808);
                    const ulonglong2 q1 = LD2(rowB + 816);
                    const u64 a4 = LD1(rowB + 832);
                    PMID(4, a1, q1, a4);
                }
                {   // dy=+2 : p7..11
                    const ulonglong2 q0 = LD2(rowB + 960), q1 = LD2(rowB + 976), q2 = LD2(rowB + 992);
                    PROW(7, q0, q1, q2);
                }
                {   // dy=+4 : p12..16
                    const ulonglong2 q0 = LD2(rowB + 1280), q1 = LD2(rowB + 1296), q2 = LD2(rowB + 1312);
                    PROW(12, q0, q1, q2);
                }
            }
        }
        bC = (bC == 2) ? 0 : bC + 1;
    }

    // ---- epilogue: inverse prev norms ----
    if (tid < 240) {
        float* ssp = (float*)(smem + SM_SSP);
        const float a = FL(sqL), b = FH(sqL), c = FL(sqH), d = FH(sqH);
        float4 r;
        r.x = a > 0.f ? rsqrtf(a) : 0.f;
        r.y = b > 0.f ? rsqrtf(b) : 0.f;
        r.z = c > 0.f ? rsqrtf(c) : 0.f;
        r.w = d > 0.f ? rsqrtf(d) : 0.f;
        ((float4*)ssp)[tid] = r;
    }
    __syncthreads();

    const float ic0 = rsqrtf(FL(ssqL));
    const float ic1 = rsqrtf(FH(ssqL));
    const float ic2 = rsqrtf(FL(ssqH));
    const float ic3 = rsqrtf(FH(ssqH));
    const u64 invL = PK(__float_as_uint(ic0), __float_as_uint(ic1));
    const u64 invH = PK(__float_as_uint(ic2), __float_as_uint(ic3));

    const char* srow = smem + SM_SSP + rowOff;
    char* outPix = (char*)(out + ((size_t)bb * 33 * HH + (y0 + ty)) * WW + x0 + tx4);

#define ESTP(OPL, PI, BL, BH) do { \
    ulonglong2 _r; \
    _r.x = M2(M2(pL[PI], invL), (BL)); \
    _r.y = M2(M2(pH[PI], invH), (BH)); \
    *(ulonglong2*)(outPix + (size_t)(OPL) * (PLANE * 4)) = _r; } while (0)

#define EROWF(ROFF, OPL, PI) do { \
    const ulonglong2 q0 = LD2(srow + (ROFF)), q1 = LD2(srow + (ROFF) + 16), \
                     q2 = LD2(srow + (ROFF) + 32); \
    ESTP(OPL + 0, PI + 0, q0.x, q0.y); \
    ESTP(OPL + 1, PI + 1, q0.y, q1.x); \
    ESTP(OPL + 2, PI + 2, q1.x, q1.y); \
    ESTP(OPL + 3, PI + 3, q1.y, q2.x); \
    ESTP(OPL + 4, PI + 4, q2.x, q2.y); } while (0)

#define EMID(ROFF, OPL, PI) do { \
    const u64 a1 = LD1(srow + (ROFF) - 8); \
    const ulonglong2 q1 = LD2(srow + (ROFF)); \
    const u64 a4 = LD1(srow + (ROFF) + 16); \
    const u64 P34 = PK(HIW(a1), LOW(q1.x)); \
    const u64 P56 = PK(HIW(q1.x), LOW(q1.y)); \
    const u64 P78 = PK(HIW(q1.y), LOW(a4)); \
    ESTP(OPL + 0, PI + 0, P34, P56); \
    ESTP(OPL + 1, PI + 1, q1.x, q1.y); \
    ESTP(OPL + 2, PI + 2, P56, P78); } while (0)

    if (wg == 0) {
        EROWF(0, 0, 0);       // dy=-4: o0..4
        EROWF(320, 5, 5);     // dy=-2: o5..9
        EMID(496, 10, 10);    // dy=-1: o10..12
        {                     // dy=0 dx<0: o13,14,15
            const ulonglong2 q0 = LD2(srow + 640), q1 = LD2(srow + 656);
            ESTP(13, 13, q0.x, q0.y);
            ESTP(14, 14, q0.y, q1.x);
            const u64 P34 = PK(HIW(q0.y), LOW(q1.x));
            const u64 P56 = PK(HIW(q1.x), LOW(q1.y));
            ESTP(15, 15, P34, P56);
        }
    } else {
        {                     // dy=0 dx>=0: o16..19
            const ulonglong2 q1 = LD2(srow + 656), q2 = LD2(srow + 672);
            ESTP(16, 0, q1.x, q1.y);
            const u64 P56 = PK(HIW(q1.x), LOW(q1.y));
            const u64 P78 = PK(HIW(q1.y), LOW(q2.x));
            ESTP(17, 1, P56, P78);
            ESTP(18, 2, q1.y, q2.x);
            ESTP(19, 3, q2.x, q2.y);
        }
        EMID(816, 20, 4);     // dy=+1: o20..22
        EROWF(960, 23, 7);    // dy=+2: o23..27
        EROWF(1280, 28, 12);  // dy=+4: o28..32
    }
}

extern "C" void kernel_launch(void* const* d_in, const int* in_sizes, int n_in,
                              void* d_out, int out_size)
{
    const float* curr = (const float*)d_in[0];
    const float* prev = (const float*)d_in[1];
    float* out = (float*)d_out;

    cudaFuncSetAttribute(corr_kernel, cudaFuncAttributeMaxDynamicSharedMemorySize, SMEM_BYTES);

    dim3 grid(WW / TILE_W, HH / TILE_H, BB);   // 6 x 8 x 8 = 384 blocks
    corr_kernel<<<grid, NT, SMEM_BYTES>>>(curr, prev, out);
}